// round 11
// baseline (speedup 1.0000x reference)
#include <cuda_runtime.h>
#include <cuda_bf16.h>
#include <math.h>
#include <stdint.h>

#define BATCH 4
#define C     128
#define H     128
#define W     128
#define P     (H*W)      // 16384
#define O     256
#define MID   32
#define KK    49
#define KWID  392
#define G     8
#define GC    16
#define EPS   1e-6f

// ---- scratch (device globals) ----
__device__ float g_x1[BATCH*C*P];
__device__ float g_mu1[BATCH*P];
__device__ float g_rs1[BATCH*P];
__device__ __align__(16) __nv_bfloat16 g_Whi[512*C];  // [conv(256); map(256)] x C
__device__ __align__(16) __nv_bfloat16 g_Wlo[512*C];

__device__ __forceinline__ float gelu_exact(float v){
    return 0.5f*v*(1.0f + erff(v*0.70710678118654752f));
}
__device__ __forceinline__ uint32_t smem_u32(const void* p){
    uint32_t a;
    asm("{ .reg .u64 t; cvta.to.shared.u64 t, %1; cvt.u32.u64 %0, t; }" : "=r"(a) : "l"(p));
    return a;
}
__device__ __forceinline__ void ldm4(uint32_t* r, uint32_t addr){
    asm volatile("ldmatrix.sync.aligned.m8n8.x4.shared.b16 {%0,%1,%2,%3}, [%4];"
        : "=r"(r[0]),"=r"(r[1]),"=r"(r[2]),"=r"(r[3]) : "r"(addr));
}
__device__ __forceinline__ void mma16816(float* d, const uint32_t* a, const uint32_t* b){
    asm volatile("mma.sync.aligned.m16n8k16.row.col.f32.bf16.bf16.f32 "
        "{%0,%1,%2,%3}, {%4,%5,%6,%7}, {%8,%9}, {%0,%1,%2,%3};"
        : "+f"(d[0]),"+f"(d[1]),"+f"(d[2]),"+f"(d[3])
        : "r"(a[0]),"r"(a[1]),"r"(a[2]),"r"(a[3]), "r"(b[0]),"r"(b[1]));
}
__device__ __forceinline__ void cp_async16(uint32_t dst, const void* src){
    asm volatile("cp.async.cg.shared.global [%0], [%1], 16;" :: "r"(dst), "l"(src));
}
#define CP_COMMIT() asm volatile("cp.async.commit_group;" ::: "memory")
#define CP_WAIT0()  asm volatile("cp.async.wait_group 0;" ::: "memory")

// packed-pair layout: 2 logical rows per 128B physical row, 4 16B units of K
// each; XOR swizzle -> conflict-free ldmatrix over 8 consecutive rows.
__device__ __forceinline__ uint32_t pphys(int row, int uu){
    uint32_t pr = (uint32_t)row >> 1;
    uint32_t slot = (((uint32_t)row & 1u)*4u + (uint32_t)uu) ^ (pr & 7u);
    return pr*128u + slot*16u;
}

// ---------------------------------------------------------------------------
// K0: split conv/map weights into bf16 hi/lo
// ---------------------------------------------------------------------------
__global__ void k_prepw(const float* __restrict__ conv_w,
                        const float* __restrict__ map_w){
    int idx = blockIdx.x*256 + threadIdx.x;
    int r = idx >> 7, c = idx & 127;
    float w = (r < 256) ? conv_w[r*C + c] : map_w[(r-256)*C + c];
    __nv_bfloat16 hi = __float2bfloat16(w);
    g_Whi[idx] = hi;
    g_Wlo[idx] = __float2bfloat16(w - __bfloat162float(hi));
}

// ---------------------------------------------------------------------------
// K1: FUSED mid-MLP (SIMT) + wkv via mma.sync + involution + LN1 stats.
//  CTA = 32x8 px (256 thr, 1 px/thread).
//  NOTE: wkv_g row stride 258 (EVEN) — required for 8B-aligned float2 stores.
// ---------------------------------------------------------------------------
#define WKV_STR  258
#define IG_W2H   0u
#define IG_W2L   32768u
#define IG_MIDH  65536u
#define IG_MIDL  81920u
#define IG_WKV   98304u
#define IG_XS    (98304u + 64u*WKV_STR*4u)       // 164352
#define SMEM_IG  (164352 + 4*544*4)              // 173056
#define XS_STRIDE 544

__global__ void __launch_bounds__(256,1) k_invgen(
    const float* __restrict__ x,
    const float* __restrict__ w1, const float* __restrict__ b1,
    const float* __restrict__ w2, const float* __restrict__ b2)
{
    extern __shared__ char dsm[];
    __shared__ float b1s[MID];
    __shared__ float b2s[KWID];

    float* wkv_g = (float*)(dsm + IG_WKV);       // [64][WKV_STR]
    float* w1t   = (float*)(dsm + IG_WKV);       // alias, phase-1 only
    float* xs    = (float*)(dsm + IG_XS);

    int tid = threadIdx.x;
    int l   = tid & 31;
    int wid = tid >> 5;
    int tx = tid & 31;
    int ty = tid >> 5;
    int w0 = blockIdx.x*32;
    int h0 = blockIdx.y*8;
    int b  = blockIdx.z;
    int p  = (h0+ty)*W + (w0+tx);
    const float* xb = x + (size_t)b*C*P;

    // ---- stage W2 as bf16 hi/lo, rows padded 49->64 with zeros ----
    for (int i = tid; i < 512*32; i += 256){
        int g   = i >> 11;
        int row = (i >> 5) & 63;
        int k   = i & 31;
        float w = (row < KK) ? w2[(g*KK + row)*MID + k] : 0.f;
        __nv_bfloat16 hi = __float2bfloat16(w);
        __nv_bfloat16 lo = __float2bfloat16(w - __bfloat162float(hi));
        uint32_t off = (uint32_t)g*4096u + pphys(row, k>>3) + (uint32_t)(k&7)*2u;
        *(__nv_bfloat16*)(dsm + IG_W2H + off) = hi;
        *(__nv_bfloat16*)(dsm + IG_W2L + off) = lo;
    }
    // w1 transposed [c][m]
    for (int i = tid; i < MID*C; i += 256){
        int m = i >> 7, c = i & 127;
        w1t[c*MID + m] = w1[i];
    }
    for (int i = tid; i < KWID; i += 256) b2s[i] = b2[i];
    if (tid < MID) b1s[tid] = b1[tid];
    __syncthreads();

    // ---- phase 1: mid = relu(W1 x + b1) ----
    float mid[MID];
    #pragma unroll
    for (int m=0;m<MID;m++) mid[m] = b1s[m];
    for (int c=0;c<C;c++){
        float xv = xb[c*P + p];
        const float* wr = &w1t[c*MID];
        #pragma unroll
        for (int m=0;m<MID;m++) mid[m] += wr[m]*xv;
    }
    #pragma unroll
    for (int m=0;m<MID;m++) mid[m] = fmaxf(mid[m], 0.f);

    __syncthreads();   // all phase-1 reads of w1t done before wkv_g overwrites

    // store mid as bf16 hi/lo in packed-pair layout (px = tid)
    #pragma unroll
    for (int uu=0; uu<4; uu++){
        uint32_t vh[4], vl[4];
        #pragma unroll
        for (int q=0;q<4;q++){
            float a0 = mid[uu*8 + q*2], a1 = mid[uu*8 + q*2 + 1];
            __nv_bfloat16 h0_ = __float2bfloat16(a0);
            __nv_bfloat16 h1_ = __float2bfloat16(a1);
            __nv_bfloat16 l0_ = __float2bfloat16(a0 - __bfloat162float(h0_));
            __nv_bfloat16 l1_ = __float2bfloat16(a1 - __bfloat162float(h1_));
            vh[q] = (uint32_t)*(uint16_t*)&h0_ | ((uint32_t)*(uint16_t*)&h1_ << 16);
            vl[q] = (uint32_t)*(uint16_t*)&l0_ | ((uint32_t)*(uint16_t*)&l1_ << 16);
        }
        uint32_t off = pphys(tid, uu);
        *(uint4*)(dsm + IG_MIDH + off) = make_uint4(vh[0],vh[1],vh[2],vh[3]);
        *(uint4*)(dsm + IG_MIDL + off) = make_uint4(vl[0],vl[1],vl[2],vl[3]);
    }
    __syncthreads();   // mid ready

    uint32_t base = smem_u32(dsm);
    int a_r = (l&7) + ((l>>3)&1)*8;
    int a_u = l>>4;
    int b_r = (l&7) + ((l>>4)&1)*8;
    int b_u = (l>>3)&1;
    int n0  = wid*32;

    float s1 = 0.f, s2 = 0.f;
    for (int g=0; g<G; g++){
        // ---- wkv_g = W2_g @ mid  (64x256, 3-term bf16) ----
        float acc[4][4][4];
        #pragma unroll
        for (int i=0;i<4;i++)
            #pragma unroll
            for (int j=0;j<4;j++)
                #pragma unroll
                for (int k=0;k<4;k++) acc[i][j][k] = 0.f;

        #pragma unroll
        for (int ks=0; ks<2; ks++){
            uint32_t Ah[4][4], Al[4][4];
            #pragma unroll
            for (int i=0;i<4;i++){
                uint32_t off = (uint32_t)g*4096u + pphys(16*i + a_r, ks*2 + a_u);
                ldm4(Ah[i], base + IG_W2H + off);
                ldm4(Al[i], base + IG_W2L + off);
            }
            uint32_t Bh[8], Bl[8];
            #pragma unroll
            for (int j2=0;j2<2;j2++){
                uint32_t off = pphys(n0 + 16*j2 + b_r, ks*2 + b_u);
                ldm4(&Bh[j2*4], base + IG_MIDH + off);
                ldm4(&Bl[j2*4], base + IG_MIDL + off);
            }
            #pragma unroll
            for (int i=0;i<4;i++)
                #pragma unroll
                for (int j=0;j<4;j++){
                    mma16816(acc[i][j], Ah[i], &Bh[j*2]);
                    mma16816(acc[i][j], Ah[i], &Bl[j*2]);
                    mma16816(acc[i][j], Al[i], &Bh[j*2]);
                }
        }
        if (g == 0) __syncthreads();   // phase-1 wkv_g alias fully dead
        // write to wkv_g[64][WKV_STR]
        #pragma unroll
        for (int i=0;i<4;i++){
            int row = 16*i + (l>>2);
            #pragma unroll
            for (int j=0;j<4;j++){
                int col = n0 + 8*j + 2*(l&3);
                *(float2*)&wkv_g[row*WKV_STR + col]     = make_float2(acc[i][j][0], acc[i][j][1]);
                *(float2*)&wkv_g[(row+8)*WKV_STR + col] = make_float2(acc[i][j][2], acc[i][j][3]);
            }
        }
        __syncthreads();

        // per-thread kernel taps (+bias)
        float wkv[KK];
        #pragma unroll
        for (int kk=0; kk<KK; kk++)
            wkv[kk] = wkv_g[kk*WKV_STR + tid] + b2s[g*KK + kk];

        // ---- involution: 4 sub-rounds x 4 channels ----
        for (int sub=0; sub<4; sub++){
            int cbase = g*GC + sub*4;
            float rr[3][4];
            #pragma unroll
            for (int pos=0; pos<3; pos++){
                int e = tid + pos*256;
                if (e < 14*38){
                    int hh = e/38, ww = e - hh*38;
                    int gh = h0 + hh - 3, gw = w0 + ww - 3;
                    bool ok = (gh>=0 && gh<H && gw>=0 && gw<W);
                    const float* src = xb + gh*W + gw;
                    #pragma unroll
                    for (int ch=0; ch<4; ch++)
                        rr[pos][ch] = ok ? src[(size_t)(cbase+ch)*P] : 0.f;
                }
            }
            __syncthreads();
            #pragma unroll
            for (int pos=0; pos<3; pos++){
                int e = tid + pos*256;
                if (e < 14*38){
                    #pragma unroll
                    for (int ch=0; ch<4; ch++)
                        xs[ch*XS_STRIDE + e] = rr[pos][ch];
                }
            }
            __syncthreads();

            const float* xc0 = xs + 0*XS_STRIDE + ty*38 + tx;
            const float* xc1 = xs + 1*XS_STRIDE + ty*38 + tx;
            const float* xc2 = xs + 2*XS_STRIDE + ty*38 + tx;
            const float* xc3 = xs + 3*XS_STRIDE + ty*38 + tx;
            float a0=0.f, a1=0.f, a2=0.f, a3=0.f;
            #pragma unroll
            for (int i=0;i<7;i++)
                #pragma unroll
                for (int j=0;j<7;j++){
                    float wv = wkv[i*7+j];
                    int o = i*38 + j;
                    a0 += wv*xc0[o];
                    a1 += wv*xc1[o];
                    a2 += wv*xc2[o];
                    a3 += wv*xc3[o];
                }
            float* dst = g_x1 + ((size_t)b*C + cbase)*P + p;
            dst[0*P] = a0; dst[1*P] = a1; dst[2*P] = a2; dst[3*P] = a3;
            s1 += a0+a1+a2+a3;
            s2 += a0*a0+a1*a1+a2*a2+a3*a3;
        }
    }
    float mu  = s1 * (1.0f/128.0f);
    float var = s2 * (1.0f/128.0f) - mu*mu;
    g_mu1[b*P + p] = mu;
    g_rs1[b*P + p] = rsqrtf(var + EPS);
}

// ---------------------------------------------------------------------------
// K3: mma.sync dual GEMM, cp.async double-buffered W (32-wide K chunks,
//     packed-pair layout) + LN2/LN3 + gelu(add)
// ---------------------------------------------------------------------------
#define XA_HI 0u
#define XA_LO 16384u
#define XB_HI 32768u
#define XB_LO 49152u
#define WB    65536u
#define YSA   131072u
#define SMEM_MMA (131072 + 256*66*4)    // 198656

__global__ void __launch_bounds__(256,1) k_out_mma(
    const float* __restrict__ x,
    const float* __restrict__ ln1w, const float* __restrict__ ln1b,
    const float* __restrict__ ln2w, const float* __restrict__ ln2b,
    const float* __restrict__ mapb,
    const float* __restrict__ ln3w, const float* __restrict__ ln3b,
    float* __restrict__ out)
{
    extern __shared__ char dsm[];
    __shared__ float sred[4][2][64];
    __shared__ float muA[64], rsA[64], muB[64], rsB[64];
    __shared__ float sLn2w[256], sLn2b[256], sLn3w[256], sLn3b[256], sMapb[256];
    __shared__ float sLn1w[128], sLn1b[128];
    __shared__ float sMu1[64], sRs1[64];

    int tid = threadIdx.x;
    int l   = tid & 31;
    int wid = tid >> 5;
    int mw  = wid & 3;
    int nw  = wid >> 2;
    int m0  = mw*64;
    int n0  = nw*32;
    int blk = blockIdx.x;
    int b   = blk >> 8;
    int p0  = (blk & 255) * 64;

    const float* xb  = x    + (size_t)b*C*P + p0;
    const float* x1b = g_x1 + (size_t)b*C*P + p0;
    float* ysA = (float*)(dsm + YSA);
    uint32_t base = smem_u32(dsm);

    // prefetch W chunk 0 (br=0, chunk=0) into buf 0 — overlaps const+X staging
    #pragma unroll
    for (int q=0;q<4;q++){
        int e = tid + q*256;        // 1024 16B units
        int row = e >> 2, uu = e & 3;
        uint32_t off = pphys(row, uu);
        cp_async16(base + WB + off,          &g_Whi[row*C + uu*8]);
        cp_async16(base + WB + 16384u + off, &g_Wlo[row*C + uu*8]);
    }
    CP_COMMIT();

    sLn2w[tid] = ln2w[tid];
    sLn2b[tid] = ln2b[tid];
    sLn3w[tid] = ln3w[tid];
    sLn3b[tid] = ln3b[tid];
    sMapb[tid] = mapb[tid];
    if (tid < 128){ sLn1w[tid] = ln1w[tid]; sLn1b[tid] = ln1b[tid]; }
    if (tid < 64){
        sMu1[tid] = g_mu1[b*P + p0 + tid];
        sRs1[tid] = g_rs1[b*P + p0 + tid];
    }
    __syncthreads();

    // stage X tiles (swizzled [px][c], bf16 hi/lo)
    for (int e = tid; e < C*64; e += 256){
        int c  = e >> 6;
        int px = e & 63;
        float raw = x1b[c*P + px];
        float v = sLn1w[c] * ((raw - sMu1[px]) * sRs1[px]) + sLn1b[c];
        float av = gelu_exact(v);
        float bv = xb[c*P + px];
        uint32_t off = (uint32_t)px*256u + (uint32_t)(((c>>3) ^ (px&7))*16) + (uint32_t)((c&7)*2);
        __nv_bfloat16 ahi = __float2bfloat16(av);
        __nv_bfloat16 alo = __float2bfloat16(av - __bfloat162float(ahi));
        __nv_bfloat16 bhi = __float2bfloat16(bv);
        __nv_bfloat16 blo = __float2bfloat16(bv - __bfloat162float(bhi));
        *(__nv_bfloat16*)(dsm + XA_HI + off) = ahi;
        *(__nv_bfloat16*)(dsm + XA_LO + off) = alo;
        *(__nv_bfloat16*)(dsm + XB_HI + off) = bhi;
        *(__nv_bfloat16*)(dsm + XB_LO + off) = blo;
    }

    int a_r = (l&7) + ((l>>3)&1)*8;
    int a_u = l>>4;
    int b_r = (l&7) + ((l>>4)&1)*8;
    int b_u = (l>>3)&1;

    float acc[4][4][4];

    for (int br = 0; br < 2; br++){
        #pragma unroll
        for (int i=0;i<4;i++)
            #pragma unroll
            for (int j=0;j<4;j++)
                #pragma unroll
                for (int k=0;k<4;k++) acc[i][j][k] = 0.f;

        uint32_t xbase = base + (br ? XB_HI : XA_HI);

        for (int chunk = 0; chunk < 4; chunk++){
            int it = br*4 + chunk;
            CP_WAIT0();
            __syncthreads();
            if (it < 7){
                int nbr = (it+1) >> 2, nch = (it+1) & 3;
                uint32_t wdst = base + WB + (uint32_t)((it+1)&1)*32768u;
                #pragma unroll
                for (int q=0;q<4;q++){
                    int e = tid + q*256;
                    int row = e >> 2, uu = e & 3;
                    uint32_t off = pphys(row, uu);
                    const __nv_bfloat16* sh = &g_Whi[(nbr*256 + row)*C + nch*32 + uu*8];
                    const __nv_bfloat16* sl = &g_Wlo[(nbr*256 + row)*C + nch*32 + uu*8];
                    cp_async16(wdst + off,          sh);
                    cp_async16(wdst + 16384u + off, sl);
                }
                CP_COMMIT();
            }
            uint32_t wbuf = base + WB + (uint32_t)(it&1)*32768u;

            #pragma unroll
            for (int ks = 0; ks < 2; ks++){
                uint32_t Ah[4][4], Al[4][4];
                #pragma unroll
                for (int i=0;i<4;i++){
                    uint32_t off = pphys(m0 + 16*i + a_r, ks*2 + a_u);
                    ldm4(Ah[i], wbuf + off);
                    ldm4(Al[i], wbuf + 16384u + off);
                }
                uint32_t Bh[8], Bl[8];
                #pragma unroll
                for (int j2=0;j2<2;j2++){
                    int rowp = n0 + 16*j2 + b_r;
                    int unit = chunk*4 + ks*2 + b_u;
                    uint32_t phys = (uint32_t)rowp*256u + (uint32_t)(((unit ^ (rowp&7)))*16);
                    ldm4(&Bh[j2*4], xbase + phys);
                    ldm4(&Bl[j2*4], xbase + 16384u + phys);
                }
                #pragma unroll
                for (int i=0;i<4;i++)
                    #pragma unroll
                    for (int j=0;j<4;j++){
                        mma16816(acc[i][j], Ah[i], &Bh[j*2]);
                        mma16816(acc[i][j], Ah[i], &Bl[j*2]);
                        mma16816(acc[i][j], Al[i], &Bh[j*2]);
                    }
            }
        }

        if (br == 1){
            #pragma unroll
            for (int i=0;i<4;i++){
                float blo_ = sMapb[m0 + 16*i + (l>>2)];
                float bhi_ = sMapb[m0 + 16*i + 8 + (l>>2)];
                #pragma unroll
                for (int j=0;j<4;j++){
                    acc[i][j][0] += blo_; acc[i][j][1] += blo_;
                    acc[i][j][2] += bhi_; acc[i][j][3] += bhi_;
                }
            }
        }

        #pragma unroll
        for (int j=0;j<4;j++){
            float p0v=0.f,p1v=0.f,q0v=0.f,q1v=0.f;
            #pragma unroll
            for (int i=0;i<4;i++){
                float d0=acc[i][j][0], d1=acc[i][j][1], d2=acc[i][j][2], d3=acc[i][j][3];
                p0v += d0+d2; p1v += d1+d3;
                q0v += d0*d0+d2*d2; q1v += d1*d1+d3*d3;
            }
            #pragma unroll
            for (int off=4; off<32; off<<=1){
                p0v += __shfl_xor_sync(0xFFFFFFFF, p0v, off);
                p1v += __shfl_xor_sync(0xFFFFFFFF, p1v, off);
                q0v += __shfl_xor_sync(0xFFFFFFFF, q0v, off);
                q1v += __shfl_xor_sync(0xFFFFFFFF, q1v, off);
            }
            if (l < 4){
                int px = n0 + 8*j + 2*l;
                sred[mw][0][px]   = p0v;
                sred[mw][0][px+1] = p1v;
                sred[mw][1][px]   = q0v;
                sred[mw][1][px+1] = q1v;
            }
        }
        if (br == 0){
            #pragma unroll
            for (int i=0;i<4;i++){
                int row = m0 + 16*i + (l>>2);
                #pragma unroll
                for (int j=0;j<4;j++){
                    int col = n0 + 8*j + 2*(l&3);
                    *(float2*)&ysA[row*66 + col]     = make_float2(acc[i][j][0], acc[i][j][1]);
                    *(float2*)&ysA[(row+8)*66 + col] = make_float2(acc[i][j][2], acc[i][j][3]);
                }
            }
        }
        __syncthreads();
        if (tid < 64){
            float s1 = sred[0][0][tid]+sred[1][0][tid]+sred[2][0][tid]+sred[3][0][tid];
            float s2 = sred[0][1][tid]+sred[1][1][tid]+sred[2][1][tid]+sred[3][1][tid];
            float mu = s1*(1.f/256.f);
            float rs = rsqrtf(s2*(1.f/256.f) - mu*mu + EPS);
            if (br == 0){ muA[tid]=mu; rsA[tid]=rs; }
            else        { muB[tid]=mu; rsB[tid]=rs; }
        }
        __syncthreads();
    }

    #pragma unroll
    for (int i=0;i<4;i++){
        #pragma unroll
        for (int j=0;j<4;j++){
            int col = n0 + 8*j + 2*(l&3);
            #pragma unroll
            for (int hh=0; hh<2; hh++){
                int row = m0 + 16*i + (l>>2) + hh*8;
                float2 ya = *(float2*)&ysA[row*66 + col];
                float w2v = sLn2w[row], b2v = sLn2b[row];
                float w3v = sLn3w[row], b3v = sLn3b[row];
                float yb0 = acc[i][j][hh*2+0], yb1 = acc[i][j][hh*2+1];
                float v0 = (ya.x - muA[col  ])*rsA[col  ]*w2v + b2v;
                float v1 = (ya.y - muA[col+1])*rsA[col+1]*w2v + b2v;
                float u0 = (yb0 - muB[col  ])*rsB[col  ]*w3v + b3v;
                float u1 = (yb1 - muB[col+1])*rsB[col+1]*w3v + b3v;
                *(float2*)&ysA[row*66 + col] =
                    make_float2(gelu_exact(v0+u0), gelu_exact(v1+u1));
            }
        }
    }
    __syncthreads();

    float* outb = out + (size_t)b*O*P + p0;
    for (int e = tid; e < O*64; e += 256){
        int o = e >> 6, px = e & 63;
        outb[o*P + px] = ysA[o*66 + px];
    }
}

// ---------------------------------------------------------------------------
extern "C" void kernel_launch(void* const* d_in, const int* in_sizes, int n_in,
                              void* d_out, int out_size)
{
    const float* x     = (const float*)d_in[0];
    const float* w1    = (const float*)d_in[1];
    const float* b1    = (const float*)d_in[2];
    const float* w2    = (const float*)d_in[3];
    const float* b2    = (const float*)d_in[4];
    const float* ln1w  = (const float*)d_in[5];
    const float* ln1b  = (const float*)d_in[6];
    const float* convw = (const float*)d_in[7];
    const float* ln2w  = (const float*)d_in[8];
    const float* ln2b  = (const float*)d_in[9];
    const float* mapw  = (const float*)d_in[10];
    const float* mapb  = (const float*)d_in[11];
    const float* ln3w  = (const float*)d_in[12];
    const float* ln3b  = (const float*)d_in[13];
    float* out = (float*)d_out;

    cudaFuncSetAttribute(k_invgen,  cudaFuncAttributeMaxDynamicSharedMemorySize, SMEM_IG);
    cudaFuncSetAttribute(k_out_mma, cudaFuncAttributeMaxDynamicSharedMemorySize, SMEM_MMA);

    k_prepw<<<256, 256>>>(convw, mapw);
    dim3 g2(W/32, H/8, BATCH);
    k_invgen<<<g2, 256, SMEM_IG>>>(x, w1, b1, w2, b2);
    k_out_mma<<<BATCH*(P/64), 256, SMEM_MMA>>>(x, ln1w, ln1b, ln2w, ln2b,
                                               mapb, ln3w, ln3b, out);
}

// round 15
// speedup vs baseline: 1.0620x; 1.0620x over previous
#include <cuda_runtime.h>
#include <cuda_bf16.h>
#include <math.h>
#include <stdint.h>

#define BATCH 4
#define C     128
#define H     128
#define W     128
#define P     (H*W)      // 16384
#define O     256
#define MID   32
#define KK    49
#define KWID  392
#define G     8
#define GC    16
#define EPS   1e-6f

// ---- scratch (device globals) ----
__device__ float g_x1[BATCH*C*P];
__device__ float g_mu1[BATCH*P];
__device__ float g_rs1[BATCH*P];
__device__ __align__(16) __nv_bfloat16 g_Whi[512*C];  // [conv(256); map(256)] x C
__device__ __align__(16) __nv_bfloat16 g_Wlo[512*C];

__device__ __forceinline__ float gelu_exact(float v){
    return 0.5f*v*(1.0f + erff(v*0.70710678118654752f));
}
__device__ __forceinline__ uint32_t smem_u32(const void* p){
    uint32_t a;
    asm("{ .reg .u64 t; cvta.to.shared.u64 t, %1; cvt.u32.u64 %0, t; }" : "=r"(a) : "l"(p));
    return a;
}
__device__ __forceinline__ void ldm4(uint32_t* r, uint32_t addr){
    asm volatile("ldmatrix.sync.aligned.m8n8.x4.shared.b16 {%0,%1,%2,%3}, [%4];"
        : "=r"(r[0]),"=r"(r[1]),"=r"(r[2]),"=r"(r[3]) : "r"(addr));
}
__device__ __forceinline__ void mma16816(float* d, const uint32_t* a, const uint32_t* b){
    asm volatile("mma.sync.aligned.m16n8k16.row.col.f32.bf16.bf16.f32 "
        "{%0,%1,%2,%3}, {%4,%5,%6,%7}, {%8,%9}, {%0,%1,%2,%3};"
        : "+f"(d[0]),"+f"(d[1]),"+f"(d[2]),"+f"(d[3])
        : "r"(a[0]),"r"(a[1]),"r"(a[2]),"r"(a[3]), "r"(b[0]),"r"(b[1]));
}
__device__ __forceinline__ void cp_async16(uint32_t dst, const void* src){
    asm volatile("cp.async.cg.shared.global [%0], [%1], 16;" :: "r"(dst), "l"(src));
}
#define CP_COMMIT() asm volatile("cp.async.commit_group;" ::: "memory")
#define CP_WAIT0()  asm volatile("cp.async.wait_group 0;" ::: "memory")

// packed-pair layout: 2 logical rows per 128B physical row, 4 16B units of K
// each; XOR swizzle -> conflict-free ldmatrix over 8 consecutive rows.
__device__ __forceinline__ uint32_t pphys(int row, int uu){
    uint32_t pr = (uint32_t)row >> 1;
    uint32_t slot = (((uint32_t)row & 1u)*4u + (uint32_t)uu) ^ (pr & 7u);
    return pr*128u + slot*16u;
}

// ---------------------------------------------------------------------------
// K0: split conv/map weights into bf16 hi/lo
// ---------------------------------------------------------------------------
__global__ void k_prepw(const float* __restrict__ conv_w,
                        const float* __restrict__ map_w){
    int idx = blockIdx.x*256 + threadIdx.x;
    int r = idx >> 7, c = idx & 127;
    float w = (r < 256) ? conv_w[r*C + c] : map_w[(r-256)*C + c];
    __nv_bfloat16 hi = __float2bfloat16(w);
    g_Whi[idx] = hi;
    g_Wlo[idx] = __float2bfloat16(w - __bfloat162float(hi));
}

// ---------------------------------------------------------------------------
// K1: FUSED kernel-gen MLP + involution + LN1 stats (R6 version: SIMT wkv,
//     2 CTAs/SM). CTA = 32x8 px tile; mid[32], wkv[49] register-resident.
// ---------------------------------------------------------------------------
#define XS_STRIDE 544
__global__ void __launch_bounds__(256,2) k_invgen(
    const float* __restrict__ x,
    const float* __restrict__ w1, const float* __restrict__ b1,
    const float* __restrict__ w2, const float* __restrict__ b2)
{
    extern __shared__ float sm[];
    float* w1t = sm;                     // [c][m] transposed  : 4096
    float* w2s = w1t + MID*C;            // [kk][m]            : 12544
    float* b2s = w2s + KWID*MID;         // 392
    float* b1s = b2s + KWID;             // 32
    float* xs  = b1s + MID;              // 4 * 544

    int tid = threadIdx.x;
    int tx = tid & 31;
    int ty = tid >> 5;
    int w0 = blockIdx.x*32;
    int h0 = blockIdx.y*8;
    int b  = blockIdx.z;
    int p  = (h0+ty)*W + (w0+tx);
    const float* xb = x + (size_t)b*C*P;

    // ---- stage weights ----
    for (int i = tid; i < MID*C; i += 256){
        int m = i >> 7, c = i & 127;          // w1 is (MID, C) row-major
        w1t[c*MID + m] = w1[i];
    }
    for (int i = tid; i < KWID*MID; i += 256) w2s[i] = w2[i];
    for (int i = tid; i < KWID; i += 256) b2s[i] = b2[i];
    if (tid < MID) b1s[tid] = b1[tid];
    __syncthreads();

    // ---- phase 1: mid = relu(W1 x + b1), register-resident ----
    float mid[MID];
    #pragma unroll
    for (int m=0;m<MID;m++) mid[m] = b1s[m];
    for (int c=0;c<C;c++){
        float xv = xb[c*P + p];
        const float* wr = &w1t[c*MID];
        #pragma unroll
        for (int m=0;m<MID;m++) mid[m] += wr[m]*xv;
    }
    #pragma unroll
    for (int m=0;m<MID;m++) mid[m] = fmaxf(mid[m], 0.f);

    // ---- phase 2: per group, compute wkv then involve 16 channels ----
    float s1 = 0.f, s2 = 0.f;
    for (int g=0; g<G; g++){
        float wkv[KK];
        #pragma unroll
        for (int kk=0; kk<KK; kk++){
            float a = b2s[g*KK + kk];
            const float* wr = &w2s[(g*KK + kk)*MID];
            #pragma unroll
            for (int m=0;m<MID;m++) a += wr[m]*mid[m];
            wkv[kk] = a;
        }

        for (int sub=0; sub<4; sub++){
            int cbase = g*GC + sub*4;
            // prefetch 4-channel halo into regs (overlaps prior compute)
            float rr[3][4];
            #pragma unroll
            for (int pos=0; pos<3; pos++){
                int e = tid + pos*256;
                if (e < 14*38){
                    int hh = e/38, ww = e - hh*38;
                    int gh = h0 + hh - 3, gw = w0 + ww - 3;
                    bool ok = (gh>=0 && gh<H && gw>=0 && gw<W);
                    const float* src = xb + gh*W + gw;
                    #pragma unroll
                    for (int ch=0; ch<4; ch++)
                        rr[pos][ch] = ok ? src[(size_t)(cbase+ch)*P] : 0.f;
                }
            }
            __syncthreads();
            #pragma unroll
            for (int pos=0; pos<3; pos++){
                int e = tid + pos*256;
                if (e < 14*38){
                    #pragma unroll
                    for (int ch=0; ch<4; ch++)
                        xs[ch*XS_STRIDE + e] = rr[pos][ch];
                }
            }
            __syncthreads();

            const float* xc0 = xs + 0*XS_STRIDE + ty*38 + tx;
            const float* xc1 = xs + 1*XS_STRIDE + ty*38 + tx;
            const float* xc2 = xs + 2*XS_STRIDE + ty*38 + tx;
            const float* xc3 = xs + 3*XS_STRIDE + ty*38 + tx;
            float a0=0.f, a1=0.f, a2=0.f, a3=0.f;
            #pragma unroll
            for (int i=0;i<7;i++)
                #pragma unroll
                for (int j=0;j<7;j++){
                    float wv = wkv[i*7+j];
                    int o = i*38 + j;
                    a0 += wv*xc0[o];
                    a1 += wv*xc1[o];
                    a2 += wv*xc2[o];
                    a3 += wv*xc3[o];
                }
            float* dst = g_x1 + ((size_t)b*C + cbase)*P + p;
            dst[0*P] = a0; dst[1*P] = a1; dst[2*P] = a2; dst[3*P] = a3;
            s1 += a0+a1+a2+a3;
            s2 += a0*a0+a1*a1+a2*a2+a3*a3;
        }
    }
    float mu  = s1 * (1.0f/128.0f);
    float var = s2 * (1.0f/128.0f) - mu*mu;
    g_mu1[b*P + p] = mu;
    g_rs1[b*P + p] = rsqrtf(var + EPS);
}

// ---------------------------------------------------------------------------
// K3: mma.sync dual GEMM, cp.async double-buffered W (32-wide K chunks,
//     packed-pair layout) + LN2/LN3 + gelu(add)   (R11 version)
// ---------------------------------------------------------------------------
#define XA_HI 0u
#define XA_LO 16384u
#define XB_HI 32768u
#define XB_LO 49152u
#define WB    65536u
#define YSA   131072u
#define SMEM_MMA (131072 + 256*66*4)    // 198656

__global__ void __launch_bounds__(256,1) k_out_mma(
    const float* __restrict__ x,
    const float* __restrict__ ln1w, const float* __restrict__ ln1b,
    const float* __restrict__ ln2w, const float* __restrict__ ln2b,
    const float* __restrict__ mapb,
    const float* __restrict__ ln3w, const float* __restrict__ ln3b,
    float* __restrict__ out)
{
    extern __shared__ char dsm[];
    __shared__ float sred[4][2][64];
    __shared__ float muA[64], rsA[64], muB[64], rsB[64];
    __shared__ float sLn2w[256], sLn2b[256], sLn3w[256], sLn3b[256], sMapb[256];
    __shared__ float sLn1w[128], sLn1b[128];
    __shared__ float sMu1[64], sRs1[64];

    int tid = threadIdx.x;
    int l   = tid & 31;
    int wid = tid >> 5;
    int mw  = wid & 3;
    int nw  = wid >> 2;
    int m0  = mw*64;
    int n0  = nw*32;
    int blk = blockIdx.x;
    int b   = blk >> 8;
    int p0  = (blk & 255) * 64;

    const float* xb  = x    + (size_t)b*C*P + p0;
    const float* x1b = g_x1 + (size_t)b*C*P + p0;
    float* ysA = (float*)(dsm + YSA);
    uint32_t base = smem_u32(dsm);

    // prefetch W chunk 0 (br=0, chunk=0) into buf 0 — overlaps const+X staging
    #pragma unroll
    for (int q=0;q<4;q++){
        int e = tid + q*256;        // 1024 16B units
        int row = e >> 2, uu = e & 3;
        uint32_t off = pphys(row, uu);
        cp_async16(base + WB + off,          &g_Whi[row*C + uu*8]);
        cp_async16(base + WB + 16384u + off, &g_Wlo[row*C + uu*8]);
    }
    CP_COMMIT();

    sLn2w[tid] = ln2w[tid];
    sLn2b[tid] = ln2b[tid];
    sLn3w[tid] = ln3w[tid];
    sLn3b[tid] = ln3b[tid];
    sMapb[tid] = mapb[tid];
    if (tid < 128){ sLn1w[tid] = ln1w[tid]; sLn1b[tid] = ln1b[tid]; }
    if (tid < 64){
        sMu1[tid] = g_mu1[b*P + p0 + tid];
        sRs1[tid] = g_rs1[b*P + p0 + tid];
    }
    __syncthreads();

    // stage X tiles (swizzled [px][c], bf16 hi/lo)
    for (int e = tid; e < C*64; e += 256){
        int c  = e >> 6;
        int px = e & 63;
        float raw = x1b[c*P + px];
        float v = sLn1w[c] * ((raw - sMu1[px]) * sRs1[px]) + sLn1b[c];
        float av = gelu_exact(v);
        float bv = xb[c*P + px];
        uint32_t off = (uint32_t)px*256u + (uint32_t)(((c>>3) ^ (px&7))*16) + (uint32_t)((c&7)*2);
        __nv_bfloat16 ahi = __float2bfloat16(av);
        __nv_bfloat16 alo = __float2bfloat16(av - __bfloat162float(ahi));
        __nv_bfloat16 bhi = __float2bfloat16(bv);
        __nv_bfloat16 blo = __float2bfloat16(bv - __bfloat162float(bhi));
        *(__nv_bfloat16*)(dsm + XA_HI + off) = ahi;
        *(__nv_bfloat16*)(dsm + XA_LO + off) = alo;
        *(__nv_bfloat16*)(dsm + XB_HI + off) = bhi;
        *(__nv_bfloat16*)(dsm + XB_LO + off) = blo;
    }

    int a_r = (l&7) + ((l>>3)&1)*8;
    int a_u = l>>4;
    int b_r = (l&7) + ((l>>4)&1)*8;
    int b_u = (l>>3)&1;

    float acc[4][4][4];

    for (int br = 0; br < 2; br++){
        #pragma unroll
        for (int i=0;i<4;i++)
            #pragma unroll
            for (int j=0;j<4;j++)
                #pragma unroll
                for (int k=0;k<4;k++) acc[i][j][k] = 0.f;

        uint32_t xbase = base + (br ? XB_HI : XA_HI);

        for (int chunk = 0; chunk < 4; chunk++){
            int it = br*4 + chunk;
            CP_WAIT0();
            __syncthreads();
            if (it < 7){
                int nbr = (it+1) >> 2, nch = (it+1) & 3;
                uint32_t wdst = base + WB + (uint32_t)((it+1)&1)*32768u;
                #pragma unroll
                for (int q=0;q<4;q++){
                    int e = tid + q*256;
                    int row = e >> 2, uu = e & 3;
                    uint32_t off = pphys(row, uu);
                    const __nv_bfloat16* sh = &g_Whi[(nbr*256 + row)*C + nch*32 + uu*8];
                    const __nv_bfloat16* sl = &g_Wlo[(nbr*256 + row)*C + nch*32 + uu*8];
                    cp_async16(wdst + off,          sh);
                    cp_async16(wdst + 16384u + off, sl);
                }
                CP_COMMIT();
            }
            uint32_t wbuf = base + WB + (uint32_t)(it&1)*32768u;

            #pragma unroll
            for (int ks = 0; ks < 2; ks++){
                uint32_t Ah[4][4], Al[4][4];
                #pragma unroll
                for (int i=0;i<4;i++){
                    uint32_t off = pphys(m0 + 16*i + a_r, ks*2 + a_u);
                    ldm4(Ah[i], wbuf + off);
                    ldm4(Al[i], wbuf + 16384u + off);
                }
                uint32_t Bh[8], Bl[8];
                #pragma unroll
                for (int j2=0;j2<2;j2++){
                    int rowp = n0 + 16*j2 + b_r;
                    int unit = chunk*4 + ks*2 + b_u;
                    uint32_t phys = (uint32_t)rowp*256u + (uint32_t)(((unit ^ (rowp&7)))*16);
                    ldm4(&Bh[j2*4], xbase + phys);
                    ldm4(&Bl[j2*4], xbase + 16384u + phys);
                }
                #pragma unroll
                for (int i=0;i<4;i++)
                    #pragma unroll
                    for (int j=0;j<4;j++){
                        mma16816(acc[i][j], Ah[i], &Bh[j*2]);
                        mma16816(acc[i][j], Ah[i], &Bl[j*2]);
                        mma16816(acc[i][j], Al[i], &Bh[j*2]);
                    }
            }
        }

        if (br == 1){
            #pragma unroll
            for (int i=0;i<4;i++){
                float blo_ = sMapb[m0 + 16*i + (l>>2)];
                float bhi_ = sMapb[m0 + 16*i + 8 + (l>>2)];
                #pragma unroll
                for (int j=0;j<4;j++){
                    acc[i][j][0] += blo_; acc[i][j][1] += blo_;
                    acc[i][j][2] += bhi_; acc[i][j][3] += bhi_;
                }
            }
        }

        #pragma unroll
        for (int j=0;j<4;j++){
            float p0v=0.f,p1v=0.f,q0v=0.f,q1v=0.f;
            #pragma unroll
            for (int i=0;i<4;i++){
                float d0=acc[i][j][0], d1=acc[i][j][1], d2=acc[i][j][2], d3=acc[i][j][3];
                p0v += d0+d2; p1v += d1+d3;
                q0v += d0*d0+d2*d2; q1v += d1*d1+d3*d3;
            }
            #pragma unroll
            for (int off=4; off<32; off<<=1){
                p0v += __shfl_xor_sync(0xFFFFFFFF, p0v, off);
                p1v += __shfl_xor_sync(0xFFFFFFFF, p1v, off);
                q0v += __shfl_xor_sync(0xFFFFFFFF, q0v, off);
                q1v += __shfl_xor_sync(0xFFFFFFFF, q1v, off);
            }
            if (l < 4){
                int px = n0 + 8*j + 2*l;
                sred[mw][0][px]   = p0v;
                sred[mw][0][px+1] = p1v;
                sred[mw][1][px]   = q0v;
                sred[mw][1][px+1] = q1v;
            }
        }
        if (br == 0){
            #pragma unroll
            for (int i=0;i<4;i++){
                int row = m0 + 16*i + (l>>2);
                #pragma unroll
                for (int j=0;j<4;j++){
                    int col = n0 + 8*j + 2*(l&3);
                    *(float2*)&ysA[row*66 + col]     = make_float2(acc[i][j][0], acc[i][j][1]);
                    *(float2*)&ysA[(row+8)*66 + col] = make_float2(acc[i][j][2], acc[i][j][3]);
                }
            }
        }
        __syncthreads();
        if (tid < 64){
            float s1 = sred[0][0][tid]+sred[1][0][tid]+sred[2][0][tid]+sred[3][0][tid];
            float s2 = sred[0][1][tid]+sred[1][1][tid]+sred[2][1][tid]+sred[3][1][tid];
            float mu = s1*(1.f/256.f);
            float rs = rsqrtf(s2*(1.f/256.f) - mu*mu + EPS);
            if (br == 0){ muA[tid]=mu; rsA[tid]=rs; }
            else        { muB[tid]=mu; rsB[tid]=rs; }
        }
        __syncthreads();
    }

    #pragma unroll
    for (int i=0;i<4;i++){
        #pragma unroll
        for (int j=0;j<4;j++){
            int col = n0 + 8*j + 2*(l&3);
            #pragma unroll
            for (int hh=0; hh<2; hh++){
                int row = m0 + 16*i + (l>>2) + hh*8;
                float2 ya = *(float2*)&ysA[row*66 + col];
                float w2v = sLn2w[row], b2v = sLn2b[row];
                float w3v = sLn3w[row], b3v = sLn3b[row];
                float yb0 = acc[i][j][hh*2+0], yb1 = acc[i][j][hh*2+1];
                float v0 = (ya.x - muA[col  ])*rsA[col  ]*w2v + b2v;
                float v1 = (ya.y - muA[col+1])*rsA[col+1]*w2v + b2v;
                float u0 = (yb0 - muB[col  ])*rsB[col  ]*w3v + b3v;
                float u1 = (yb1 - muB[col+1])*rsB[col+1]*w3v + b3v;
                *(float2*)&ysA[row*66 + col] =
                    make_float2(gelu_exact(v0+u0), gelu_exact(v1+u1));
            }
        }
    }
    __syncthreads();

    float* outb = out + (size_t)b*O*P + p0;
    for (int e = tid; e < O*64; e += 256){
        int o = e >> 6, px = e & 63;
        outb[o*P + px] = ysA[o*66 + px];
    }
}

// ---------------------------------------------------------------------------
extern "C" void kernel_launch(void* const* d_in, const int* in_sizes, int n_in,
                              void* d_out, int out_size)
{
    const float* x     = (const float*)d_in[0];
    const float* w1    = (const float*)d_in[1];
    const float* b1    = (const float*)d_in[2];
    const float* w2    = (const float*)d_in[3];
    const float* b2    = (const float*)d_in[4];
    const float* ln1w  = (const float*)d_in[5];
    const float* ln1b  = (const float*)d_in[6];
    const float* convw = (const float*)d_in[7];
    const float* ln2w  = (const float*)d_in[8];
    const float* ln2b  = (const float*)d_in[9];
    const float* mapw  = (const float*)d_in[10];
    const float* mapb  = (const float*)d_in[11];
    const float* ln3w  = (const float*)d_in[12];
    const float* ln3b  = (const float*)d_in[13];
    float* out = (float*)d_out;

    const int smem_invgen = (MID*C + KWID*MID + KWID + MID + 4*XS_STRIDE) * 4;
    cudaFuncSetAttribute(k_invgen,  cudaFuncAttributeMaxDynamicSharedMemorySize, smem_invgen);
    cudaFuncSetAttribute(k_out_mma, cudaFuncAttributeMaxDynamicSharedMemorySize, SMEM_MMA);

    k_prepw<<<256, 256>>>(convw, mapw);
    dim3 g2(W/32, H/8, BATCH);
    k_invgen<<<g2, 256, smem_invgen>>>(x, w1, b1, w2, b2);
    k_out_mma<<<BATCH*(P/64), 256, SMEM_MMA>>>(x, ln1w, ln1b, ln2w, ln2b,
                                               mapb, ln3w, ln3b, out);
}

// round 17
// speedup vs baseline: 1.1008x; 1.0365x over previous
#include <cuda_runtime.h>
#include <cuda_bf16.h>
#include <math.h>
#include <stdint.h>

#define BATCH 4
#define C     128
#define H     128
#define W     128
#define P     (H*W)      // 16384
#define O     256
#define MID   32
#define KK    49
#define KWID  392
#define G     8
#define GC    16
#define EPS   1e-6f

// ---- scratch (device globals) ----
__device__ float g_x1[BATCH*C*P];
__device__ float g_mu1[BATCH*P];
__device__ float g_rs1[BATCH*P];
__device__ __align__(16) __nv_bfloat16 g_Whi[512*C];  // [conv(256); map(256)] x C
__device__ __align__(16) __nv_bfloat16 g_Wlo[512*C];

__device__ __forceinline__ float gelu_exact(float v){
    return 0.5f*v*(1.0f + erff(v*0.70710678118654752f));
}
__device__ __forceinline__ uint32_t smem_u32(const void* p){
    uint32_t a;
    asm("{ .reg .u64 t; cvta.to.shared.u64 t, %1; cvt.u32.u64 %0, t; }" : "=r"(a) : "l"(p));
    return a;
}
__device__ __forceinline__ void ldm4(uint32_t* r, uint32_t addr){
    asm volatile("ldmatrix.sync.aligned.m8n8.x4.shared.b16 {%0,%1,%2,%3}, [%4];"
        : "=r"(r[0]),"=r"(r[1]),"=r"(r[2]),"=r"(r[3]) : "r"(addr));
}
__device__ __forceinline__ void mma16816(float* d, const uint32_t* a, const uint32_t* b){
    asm volatile("mma.sync.aligned.m16n8k16.row.col.f32.bf16.bf16.f32 "
        "{%0,%1,%2,%3}, {%4,%5,%6,%7}, {%8,%9}, {%0,%1,%2,%3};"
        : "+f"(d[0]),"+f"(d[1]),"+f"(d[2]),"+f"(d[3])
        : "r"(a[0]),"r"(a[1]),"r"(a[2]),"r"(a[3]), "r"(b[0]),"r"(b[1]));
}
__device__ __forceinline__ void cp_async16(uint32_t dst, const void* src){
    asm volatile("cp.async.cg.shared.global [%0], [%1], 16;" :: "r"(dst), "l"(src));
}
#define CP_COMMIT() asm volatile("cp.async.commit_group;" ::: "memory")
#define CP_WAIT0()  asm volatile("cp.async.wait_group 0;" ::: "memory")

// packed-pair layout: 2 logical rows per 128B physical row, 4 16B units of K
// each; XOR swizzle -> conflict-free ldmatrix over 8 consecutive rows.
__device__ __forceinline__ uint32_t pphys(int row, int uu){
    uint32_t pr = (uint32_t)row >> 1;
    uint32_t slot = (((uint32_t)row & 1u)*4u + (uint32_t)uu) ^ (pr & 7u);
    return pr*128u + slot*16u;
}

// ---------------------------------------------------------------------------
// K0: split conv/map weights into bf16 hi/lo
// ---------------------------------------------------------------------------
__global__ void k_prepw(const float* __restrict__ conv_w,
                        const float* __restrict__ map_w){
    int idx = blockIdx.x*256 + threadIdx.x;
    int r = idx >> 7, c = idx & 127;
    float w = (r < 256) ? conv_w[r*C + c] : map_w[(r-256)*C + c];
    __nv_bfloat16 hi = __float2bfloat16(w);
    g_Whi[idx] = hi;
    g_Wlo[idx] = __float2bfloat16(w - __bfloat162float(hi));
}

// ---------------------------------------------------------------------------
// K1: FUSED kernel-gen MLP + involution + LN1 stats (unchanged, known-good)
// ---------------------------------------------------------------------------
#define XS_STRIDE 544
__global__ void __launch_bounds__(256,2) k_invgen(
    const float* __restrict__ x,
    const float* __restrict__ w1, const float* __restrict__ b1,
    const float* __restrict__ w2, const float* __restrict__ b2)
{
    extern __shared__ float sm[];
    float* w1t = sm;
    float* w2s = w1t + MID*C;
    float* b2s = w2s + KWID*MID;
    float* b1s = b2s + KWID;
    float* xs  = b1s + MID;

    int tid = threadIdx.x;
    int tx = tid & 31;
    int ty = tid >> 5;
    int w0 = blockIdx.x*32;
    int h0 = blockIdx.y*8;
    int b  = blockIdx.z;
    int p  = (h0+ty)*W + (w0+tx);
    const float* xb = x + (size_t)b*C*P;

    for (int i = tid; i < MID*C; i += 256){
        int m = i >> 7, c = i & 127;
        w1t[c*MID + m] = w1[i];
    }
    for (int i = tid; i < KWID*MID; i += 256) w2s[i] = w2[i];
    for (int i = tid; i < KWID; i += 256) b2s[i] = b2[i];
    if (tid < MID) b1s[tid] = b1[tid];
    __syncthreads();

    float mid[MID];
    #pragma unroll
    for (int m=0;m<MID;m++) mid[m] = b1s[m];
    for (int c=0;c<C;c++){
        float xv = xb[c*P + p];
        const float* wr = &w1t[c*MID];
        #pragma unroll
        for (int m=0;m<MID;m++) mid[m] += wr[m]*xv;
    }
    #pragma unroll
    for (int m=0;m<MID;m++) mid[m] = fmaxf(mid[m], 0.f);

    float s1 = 0.f, s2 = 0.f;
    for (int g=0; g<G; g++){
        float wkv[KK];
        #pragma unroll
        for (int kk=0; kk<KK; kk++){
            float a = b2s[g*KK + kk];
            const float* wr = &w2s[(g*KK + kk)*MID];
            #pragma unroll
            for (int m=0;m<MID;m++) a += wr[m]*mid[m];
            wkv[kk] = a;
        }

        for (int sub=0; sub<4; sub++){
            int cbase = g*GC + sub*4;
            float rr[3][4];
            #pragma unroll
            for (int pos=0; pos<3; pos++){
                int e = tid + pos*256;
                if (e < 14*38){
                    int hh = e/38, ww = e - hh*38;
                    int gh = h0 + hh - 3, gw = w0 + ww - 3;
                    bool ok = (gh>=0 && gh<H && gw>=0 && gw<W);
                    const float* src = xb + gh*W + gw;
                    #pragma unroll
                    for (int ch=0; ch<4; ch++)
                        rr[pos][ch] = ok ? src[(size_t)(cbase+ch)*P] : 0.f;
                }
            }
            __syncthreads();
            #pragma unroll
            for (int pos=0; pos<3; pos++){
                int e = tid + pos*256;
                if (e < 14*38){
                    #pragma unroll
                    for (int ch=0; ch<4; ch++)
                        xs[ch*XS_STRIDE + e] = rr[pos][ch];
                }
            }
            __syncthreads();

            const float* xc0 = xs + 0*XS_STRIDE + ty*38 + tx;
            const float* xc1 = xs + 1*XS_STRIDE + ty*38 + tx;
            const float* xc2 = xs + 2*XS_STRIDE + ty*38 + tx;
            const float* xc3 = xs + 3*XS_STRIDE + ty*38 + tx;
            float a0=0.f, a1=0.f, a2=0.f, a3=0.f;
            #pragma unroll
            for (int i=0;i<7;i++)
                #pragma unroll
                for (int j=0;j<7;j++){
                    float wv = wkv[i*7+j];
                    int o = i*38 + j;
                    a0 += wv*xc0[o];
                    a1 += wv*xc1[o];
                    a2 += wv*xc2[o];
                    a3 += wv*xc3[o];
                }
            float* dst = g_x1 + ((size_t)b*C + cbase)*P + p;
            dst[0*P] = a0; dst[1*P] = a1; dst[2*P] = a2; dst[3*P] = a3;
            s1 += a0+a1+a2+a3;
            s2 += a0*a0+a1*a1+a2*a2+a3*a3;
        }
    }
    float mu  = s1 * (1.0f/128.0f);
    float var = s2 * (1.0f/128.0f) - mu*mu;
    g_mu1[b*P + p] = mu;
    g_rs1[b*P + p] = rsqrtf(var + EPS);
}

// ---------------------------------------------------------------------------
// K3: mma.sync dual GEMM, 32-px tile, single-buffered W, ~99KB smem
//     -> 2 CTAs/SM. 8 m-warps x 32 px. LN2/LN3 + gelu(add) epilogue.
// ---------------------------------------------------------------------------
#define PXT2  32
#define XA_HI 0u
#define XA_LO 8192u
#define XB_HI 16384u
#define XB_LO 24576u
#define WB    32768u                      // hi @ WB, lo @ WB+16384
#define YSA   65536u
#define SMEM_MMA (65536 + 256*34*4)       // 100352

__global__ void __launch_bounds__(256,2) k_out_mma(
    const float* __restrict__ x,
    const float* __restrict__ ln1w, const float* __restrict__ ln1b,
    const float* __restrict__ ln2w, const float* __restrict__ ln2b,
    const float* __restrict__ mapb,
    const float* __restrict__ ln3w, const float* __restrict__ ln3b,
    float* __restrict__ out)
{
    extern __shared__ char dsm[];
    __shared__ float sred[8][2][PXT2];
    __shared__ float muA[PXT2], rsA[PXT2], muB[PXT2], rsB[PXT2];
    __shared__ float sLn2w[256], sLn2b[256], sLn3w[256], sLn3b[256], sMapb[256];
    __shared__ float sLn1w[128], sLn1b[128];
    __shared__ float sMu1[PXT2], sRs1[PXT2];

    int tid = threadIdx.x;
    int l   = tid & 31;
    int wid = tid >> 5;
    int m0  = wid*32;
    int blk = blockIdx.x;
    int b   = blk >> 9;                   // 512 tiles per batch
    int p0  = (blk & 511) * PXT2;

    const float* xb  = x    + (size_t)b*C*P + p0;
    const float* x1b = g_x1 + (size_t)b*C*P + p0;
    float* ysA = (float*)(dsm + YSA);
    uint32_t base = smem_u32(dsm);

    // prefetch W chunk 0 (br=0) — overlaps const+X staging
    #pragma unroll
    for (int q=0;q<4;q++){
        int e = tid + q*256;              // 1024 16B units per buffer
        int row = e >> 2, uu = e & 3;
        uint32_t off = pphys(row, uu);
        cp_async16(base + WB + off,          &g_Whi[row*C + uu*8]);
        cp_async16(base + WB + 16384u + off, &g_Wlo[row*C + uu*8]);
    }
    CP_COMMIT();

    sLn2w[tid] = ln2w[tid];
    sLn2b[tid] = ln2b[tid];
    sLn3w[tid] = ln3w[tid];
    sLn3b[tid] = ln3b[tid];
    sMapb[tid] = mapb[tid];
    if (tid < 128){ sLn1w[tid] = ln1w[tid]; sLn1b[tid] = ln1b[tid]; }
    if (tid < PXT2){
        sMu1[tid] = g_mu1[b*P + p0 + tid];
        sRs1[tid] = g_rs1[b*P + p0 + tid];
    }
    __syncthreads();

    // stage X tiles (swizzled [px][c], bf16 hi/lo); 4096 elems / 256 thr
    for (int e = tid; e < C*PXT2; e += 256){
        int c  = e >> 5;
        int px = e & 31;
        float raw = x1b[c*P + px];
        float v = sLn1w[c] * ((raw - sMu1[px]) * sRs1[px]) + sLn1b[c];
        float av = gelu_exact(v);
        float bv = xb[c*P + px];
        uint32_t off = (uint32_t)px*256u + (uint32_t)(((c>>3) ^ (px&7))*16) + (uint32_t)((c&7)*2);
        __nv_bfloat16 ahi = __float2bfloat16(av);
        __nv_bfloat16 alo = __float2bfloat16(av - __bfloat162float(ahi));
        __nv_bfloat16 bhi = __float2bfloat16(bv);
        __nv_bfloat16 blo = __float2bfloat16(bv - __bfloat162float(bhi));
        *(__nv_bfloat16*)(dsm + XA_HI + off) = ahi;
        *(__nv_bfloat16*)(dsm + XA_LO + off) = alo;
        *(__nv_bfloat16*)(dsm + XB_HI + off) = bhi;
        *(__nv_bfloat16*)(dsm + XB_LO + off) = blo;
    }

    int a_r = (l&7) + ((l>>3)&1)*8;
    int a_u = l>>4;
    int b_r = (l&7) + ((l>>4)&1)*8;
    int b_u = (l>>3)&1;

    float acc[2][4][4];

    for (int br = 0; br < 2; br++){
        #pragma unroll
        for (int i=0;i<2;i++)
            #pragma unroll
            for (int j=0;j<4;j++)
                #pragma unroll
                for (int k=0;k<4;k++) acc[i][j][k] = 0.f;

        uint32_t xbase = base + (br ? XB_HI : XA_HI);

        for (int chunk = 0; chunk < 4; chunk++){
            int it = br*4 + chunk;
            if (it > 0){
                __syncthreads();          // prior chunk's ldm reads complete
                #pragma unroll
                for (int q=0;q<4;q++){
                    int e = tid + q*256;
                    int row = e >> 2, uu = e & 3;
                    uint32_t off = pphys(row, uu);
                    const __nv_bfloat16* sh = &g_Whi[(br*256 + row)*C + chunk*32 + uu*8];
                    const __nv_bfloat16* sl = &g_Wlo[(br*256 + row)*C + chunk*32 + uu*8];
                    cp_async16(base + WB + off,          sh);
                    cp_async16(base + WB + 16384u + off, sl);
                }
                CP_COMMIT();
            }
            CP_WAIT0();
            __syncthreads();

            #pragma unroll
            for (int ks = 0; ks < 2; ks++){
                uint32_t Ah[2][4], Al[2][4];
                #pragma unroll
                for (int i=0;i<2;i++){
                    uint32_t off = pphys(m0 + 16*i + a_r, ks*2 + a_u);
                    ldm4(Ah[i], base + WB + off);
                    ldm4(Al[i], base + WB + 16384u + off);
                }
                uint32_t Bh[8], Bl[8];
                #pragma unroll
                for (int j2=0;j2<2;j2++){
                    int rowp = 16*j2 + b_r;
                    int unit = chunk*4 + ks*2 + b_u;
                    uint32_t phys = (uint32_t)rowp*256u + (uint32_t)(((unit ^ (rowp&7)))*16);
                    ldm4(&Bh[j2*4], xbase + phys);
                    ldm4(&Bl[j2*4], xbase + 8192u + phys);
                }
                #pragma unroll
                for (int i=0;i<2;i++)
                    #pragma unroll
                    for (int j=0;j<4;j++){
                        mma16816(acc[i][j], Ah[i], &Bh[j*2]);
                        mma16816(acc[i][j], Ah[i], &Bl[j*2]);
                        mma16816(acc[i][j], Al[i], &Bh[j*2]);
                    }
            }
        }

        if (br == 1){
            #pragma unroll
            for (int i=0;i<2;i++){
                float blo_ = sMapb[m0 + 16*i + (l>>2)];
                float bhi_ = sMapb[m0 + 16*i + 8 + (l>>2)];
                #pragma unroll
                for (int j=0;j<4;j++){
                    acc[i][j][0] += blo_; acc[i][j][1] += blo_;
                    acc[i][j][2] += bhi_; acc[i][j][3] += bhi_;
                }
            }
        }

        // per-pixel partial stats over this warp's 32 rows
        #pragma unroll
        for (int j=0;j<4;j++){
            float p0v=0.f,p1v=0.f,q0v=0.f,q1v=0.f;
            #pragma unroll
            for (int i=0;i<2;i++){
                float d0=acc[i][j][0], d1=acc[i][j][1], d2=acc[i][j][2], d3=acc[i][j][3];
                p0v += d0+d2; p1v += d1+d3;
                q0v += d0*d0+d2*d2; q1v += d1*d1+d3*d3;
            }
            #pragma unroll
            for (int off=4; off<32; off<<=1){
                p0v += __shfl_xor_sync(0xFFFFFFFF, p0v, off);
                p1v += __shfl_xor_sync(0xFFFFFFFF, p1v, off);
                q0v += __shfl_xor_sync(0xFFFFFFFF, q0v, off);
                q1v += __shfl_xor_sync(0xFFFFFFFF, q1v, off);
            }
            if (l < 4){
                int px = 8*j + 2*l;
                sred[wid][0][px]   = p0v;
                sred[wid][0][px+1] = p1v;
                sred[wid][1][px]   = q0v;
                sred[wid][1][px+1] = q1v;
            }
        }
        if (br == 0){
            // park branch-A result in ysA [256][34]
            #pragma unroll
            for (int i=0;i<2;i++){
                int row = m0 + 16*i + (l>>2);
                #pragma unroll
                for (int j=0;j<4;j++){
                    int col = 8*j + 2*(l&3);
                    *(float2*)&ysA[row*34 + col]     = make_float2(acc[i][j][0], acc[i][j][1]);
                    *(float2*)&ysA[(row+8)*34 + col] = make_float2(acc[i][j][2], acc[i][j][3]);
                }
            }
        }
        __syncthreads();
        if (tid < PXT2){
            float s1 = 0.f, s2 = 0.f;
            #pragma unroll
            for (int wq=0; wq<8; wq++){
                s1 += sred[wq][0][tid];
                s2 += sred[wq][1][tid];
            }
            float mu = s1*(1.f/256.f);
            float rs = rsqrtf(s2*(1.f/256.f) - mu*mu + EPS);
            if (br == 0){ muA[tid]=mu; rsA[tid]=rs; }
            else        { muB[tid]=mu; rsB[tid]=rs; }
        }
        __syncthreads();
    }

    // final combine: gelu(LN2(yA) + LN3(yB)) into ysA
    #pragma unroll
    for (int i=0;i<2;i++){
        #pragma unroll
        for (int j=0;j<4;j++){
            int col = 8*j + 2*(l&3);
            #pragma unroll
            for (int hh=0; hh<2; hh++){
                int row = m0 + 16*i + (l>>2) + hh*8;
                float2 ya = *(float2*)&ysA[row*34 + col];
                float w2v = sLn2w[row], b2v = sLn2b[row];
                float w3v = sLn3w[row], b3v = sLn3b[row];
                float yb0 = acc[i][j][hh*2+0], yb1 = acc[i][j][hh*2+1];
                float v0 = (ya.x - muA[col  ])*rsA[col  ]*w2v + b2v;
                float v1 = (ya.y - muA[col+1])*rsA[col+1]*w2v + b2v;
                float u0 = (yb0 - muB[col  ])*rsB[col  ]*w3v + b3v;
                float u1 = (yb1 - muB[col+1])*rsB[col+1]*w3v + b3v;
                *(float2*)&ysA[row*34 + col] =
                    make_float2(gelu_exact(v0+u0), gelu_exact(v1+u1));
            }
        }
    }
    __syncthreads();

    float* outb = out + (size_t)b*O*P + p0;
    for (int e = tid; e < O*PXT2; e += 256){
        int o = e >> 5, px = e & 31;
        outb[o*P + px] = ysA[o*34 + px];
    }
}

// ---------------------------------------------------------------------------
extern "C" void kernel_launch(void* const* d_in, const int* in_sizes, int n_in,
                              void* d_out, int out_size)
{
    const float* x     = (const float*)d_in[0];
    const float* w1    = (const float*)d_in[1];
    const float* b1    = (const float*)d_in[2];
    const float* w2    = (const float*)d_in[3];
    const float* b2    = (const float*)d_in[4];
    const float* ln1w  = (const float*)d_in[5];
    const float* ln1b  = (const float*)d_in[6];
    const float* convw = (const float*)d_in[7];
    const float* ln2w  = (const float*)d_in[8];
    const float* ln2b  = (const float*)d_in[9];
    const float* mapw  = (const float*)d_in[10];
    const float* mapb  = (const float*)d_in[11];
    const float* ln3w  = (const float*)d_in[12];
    const float* ln3b  = (const float*)d_in[13];
    float* out = (float*)d_out;

    const int smem_invgen = (MID*C + KWID*MID + KWID + MID + 4*XS_STRIDE) * 4;
    cudaFuncSetAttribute(k_invgen,  cudaFuncAttributeMaxDynamicSharedMemorySize, smem_invgen);
    cudaFuncSetAttribute(k_out_mma, cudaFuncAttributeMaxDynamicSharedMemorySize, SMEM_MMA);

    k_prepw<<<256, 256>>>(convw, mapw);
    dim3 g2(W/32, H/8, BATCH);
    k_invgen<<<g2, 256, smem_invgen>>>(x, w1, b1, w2, b2);
    k_out_mma<<<BATCH*(P/PXT2), 256, SMEM_MMA>>>(x, ln1w, ln1b, ln2w, ln2b,
                                                 mapb, ln3w, ln3b, out);
}